// round 14
// baseline (speedup 1.0000x reference)
#include <cuda_runtime.h>
#include <math.h>

#define NE 100000
#define NR 400
#define NT 1000000
#define B  32
#define DH 512
#define T_STEPS 3
#define HB 148
#define SOFT_BLKS (T_STEPS * B)       // 96
#define TRANS_BLKS (NE / 32)          // 3125
#define INIT_BLKS  600
#define NWORDS ((NE + 31) / 32)       // 3125

// ---------------- device scratch (16B-aligned) ----------------
__device__ __align__(16) float g_e[T_STEPS + 1][NE * B];
__device__ __align__(16) float g_relT[T_STEPS][NR * B];
__device__ __align__(16) float g_cqA[T_STEPS][B][DH];
__device__ __align__(16) float g_logits[T_STEPS][B][NR];
__device__ int   g_argmax[T_STEPS * B];
__device__ float g_gt[B];
__device__ __align__(16) float g_sums[B];
__device__ __align__(16) float g_h[B * DH];
__device__ __align__(16) unsigned g_maskw[NWORDS];   // bit per entity (12.5 KB, L1-resident)
__device__ int   g_nact;
__device__ int   g_act[NE];
__device__ int   g_ansIdx[B];
__device__ float g_ansVal[B];
__device__ __align__(16) float g_hpart[HB][DH * B];

// ---------------- f32x2 helpers ----------------
__device__ __forceinline__ unsigned long long pk2(float v) {
    unsigned long long r;
    asm("mov.b64 %0,{%1,%1};" : "=l"(r) : "f"(v));
    return r;
}
__device__ __forceinline__ void fma2(unsigned long long& d, unsigned long long a,
                                     unsigned long long b) {
    asm("fma.rn.f32x2 %0,%1,%2,%0;" : "+l"(d) : "l"(a), "l"(b));
}
__device__ __forceinline__ void upk2(unsigned long long v, float& lo, float& hi) {
    asm("mov.b64 {%0,%1},%2;" : "=f"(lo), "=f"(hi) : "l"(v));
}
__device__ __forceinline__ float dot4(float4 a, float4 b) {
    return a.x * b.x + a.y * b.y + a.z * b.z + a.w * b.w;
}
__device__ __forceinline__ float condf(int t, int b) {
    int prev = g_argmax[(t - 1) * B + b], curr = g_argmax[t * B + b];
    int d = prev - curr; if (d < 0) d = -d;
    int mn = prev < curr ? prev : curr;
    return (d == 1 && (mn & 1) == 0) ? 1.f : 0.f;
}
__device__ __forceinline__ float m3f(int b) {
    int ns = 0;
#pragma unroll
    for (int k = 0; k < T_STEPS; k++) ns += (g_argmax[k * B + b] == 0);
    return (ns == 1) ? 1.f : 0.f;
}

// ---------------- all-steps cq: warp per output (t,b,j) ----------------
__global__ void __launch_bounds__(256) k_cq_all(const int* __restrict__ questions,
                                                const float* __restrict__ rel_emb,
                                                const float* __restrict__ step_W,
                                                const float* __restrict__ step_b) {
    cudaGridDependencySynchronize();
    int w = blockIdx.x * 8 + (threadIdx.x >> 5);
    int lane = threadIdx.x & 31;
    int j = w & (DH - 1);
    int b = (w >> 9) & (B - 1);
    int t = w >> 14;
    if (t >= T_STEPS) return;
    int qi = __ldg(questions + b);
    const float4* q = (const float4*)(rel_emb + (size_t)qi * DH);
    const float4* W = (const float4*)(step_W + (size_t)t * DH * DH + (size_t)j * DH);
    float acc = 0.f;
#pragma unroll
    for (int c = 0; c < 4; c++) {
        float4 qv = __ldg(q + lane + c * 32);
        float4 wv = __ldg(W + lane + c * 32);
        acc += dot4(qv, wv);
    }
#pragma unroll
    for (int s = 16; s > 0; s >>= 1) acc += __shfl_xor_sync(0xffffffffu, acc, s);
    if (lane == 0)
        g_cqA[t][b][j] = tanhf(acc + __ldg(step_b + t * DH + j));
}

// ---------------- all-steps rel logits: warp per output (t,b,r) ----------------
__global__ void __launch_bounds__(256) k_logits_all(const float* __restrict__ rel_emb) {
    cudaGridDependencySynchronize();
    int w = blockIdx.x * 8 + (threadIdx.x >> 5);
    int lane = threadIdx.x & 31;
    int r = w % NR;
    int tb = w / NR;
    int b = tb & (B - 1);
    int t = tb >> 5;
    if (t >= T_STEPS) return;
    const float4* q = (const float4*)&g_cqA[t][b][0];
    const float4* E = (const float4*)(rel_emb + (size_t)r * DH);
    float acc = 0.f;
#pragma unroll
    for (int c = 0; c < 4; c++) {
        float4 qv = q[lane + c * 32];
        float4 ev = __ldg(E + lane + c * 32);
        acc += dot4(qv, ev);
    }
#pragma unroll
    for (int s = 16; s > 0; s >>= 1) acc += __shfl_xor_sync(0xffffffffu, acc, s);
    if (lane == 0) g_logits[t][b][r] = acc;
}

// ---------------- fused: softmax(96 blks) | transpose e_s (bit words) | zero + findans ----------------
__global__ void __launch_bounds__(512) k_setup(const int* __restrict__ questions,
                                               const float* __restrict__ es,
                                               const float* __restrict__ ans) {
    cudaGridDependencySynchronize();
    int bx = blockIdx.x;
    int tid = threadIdx.x;
    if (bx < SOFT_BLKS) {
        __shared__ float red[512];
        __shared__ int   redi[512];
        int t = bx >> 5;
        int b = bx & 31;
        int r = tid;
        float logit = (r < NR) ? g_logits[t][b][r] : -1e30f;
        red[r] = logit; redi[r] = (r < NR) ? r : 0x7fffffff;
        __syncthreads();
        for (int s = 256; s > 0; s >>= 1) {
            if (r < s) {
                float a = red[r], c = red[r + s];
                int ia = redi[r], ic = redi[r + s];
                if (c > a || (c == a && ic < ia)) { red[r] = c; redi[r] = ic; }
            }
            __syncthreads();
        }
        float mx = red[0];
        int amax = redi[0];
        __syncthreads();
        float e = (r < NR) ? expf(logit - mx) : 0.f;
        red[r] = e;
        __syncthreads();
        for (int s = 256; s > 0; s >>= 1) {
            if (r < s) red[r] += red[r + s];
            __syncthreads();
        }
        float sum = red[0];
        if (r < NR) {
            float p = e / sum;
            g_relT[t][r * B + b] = p;
            if (t == 0 && r == questions[b]) g_gt[b] = p;
        }
        if (r == 0) g_argmax[t * B + b] = amax;
    } else if (bx < SOFT_BLKS + TRANS_BLKS) {
        __shared__ float tile[32][33];
        __shared__ unsigned wbits;
        int wb = bx - SOFT_BLKS;
        int i0 = wb * 32;
        int tx = tid & 31, ty0 = tid >> 5;
        if (tid == 0) wbits = 0u;
#pragma unroll
        for (int r = 0; r < 2; r++) {
            int ty = ty0 + r * 16;
            tile[ty][tx] = es[(size_t)ty * NE + i0 + tx];
        }
        __syncthreads();
#pragma unroll
        for (int r = 0; r < 2; r++) {
            int ty = ty0 + r * 16;
            float v = tile[tx][ty];
            g_e[0][(size_t)(i0 + ty) * B + tx] = v;
            unsigned m = __ballot_sync(0xffffffffu, v != 0.f);
            if (tx == 0 && m != 0u) atomicOr(&wbits, 1u << ty);
        }
        __syncthreads();
        if (tid == 0) g_maskw[wb] = wbits;
    } else {
        int gtid = (bx - SOFT_BLKS - TRANS_BLKS) * 512 + tid;
        int stride = INIT_BLKS * 512;
        float4 z = make_float4(0.f, 0.f, 0.f, 0.f);
        int n4 = T_STEPS * NE * B / 4;
        float4* base = (float4*)g_e[1];
        for (int i = gtid; i < n4; i += stride) base[i] = z;
        int nf4 = B * NE / 4;
        for (int i = gtid; i < nf4; i += stride) {
            float4 v = *(const float4*)&ans[(size_t)i * 4];
            if (v.x != 0.f || v.y != 0.f || v.z != 0.f || v.w != 0.f) {
                int b = i / (NE / 4);
                int e = (i - b * (NE / 4)) * 4;
                if (v.x != 0.f) { g_ansIdx[b] = e;     g_ansVal[b] = v.x; }
                if (v.y != 0.f) { g_ansIdx[b] = e + 1; g_ansVal[b] = v.y; }
                if (v.z != 0.f) { g_ansIdx[b] = e + 2; g_ansVal[b] = v.z; }
                if (v.w != 0.f) { g_ansIdx[b] = e + 3; g_ansVal[b] = v.w; }
            }
        }
        if (gtid < B) g_sums[gtid] = 0.f;
        if (gtid == 0) g_nact = 0;
    }
}

// ---------------- follow: bitmask-gated scatter (scalar thread-per-triple) ----------------
__global__ void __launch_bounds__(256) k_follow(const int* __restrict__ subj,
                                                const int* __restrict__ rel,
                                                const int* __restrict__ obj, int t) {
    cudaGridDependencySynchronize();
    int i = blockIdx.x * 256 + threadIdx.x;
    int lane = threadIdx.x & 31;
    int s = 0;
    bool act = false;
    if (i < NT) {
        s = __ldg(subj + i);
        act = (g_maskw[s >> 5] >> (s & 31)) & 1u;
    }
    unsigned m = __ballot_sync(0xffffffffu, act);
    const float* relT = g_relT[t];
    while (m) {
        int j = __ffs(m) - 1; m &= m - 1;
        int ti = __shfl_sync(0xffffffffu, i, j);
        int ts = __shfl_sync(0xffffffffu, s, j);
        int tr = __ldg(rel + ti);
        int to = __ldg(obj + ti);
        float x = g_e[t][(size_t)ts * B + lane] * relT[tr * B + lane];
        if (x != 0.f) atomicAdd(&g_e[t + 1][(size_t)to * B + lane], x);
    }
}

// ---------------- mid-step post (t = 0 or 1), full sweep, bit-word mask out ----------------
__global__ void __launch_bounds__(256) k_post(int t) {
    cudaGridDependencySynchronize();
    __shared__ unsigned wbits;
    int tid = threadIdx.x;
    int idx4 = blockIdx.x * 256 + tid;
    int b4 = idx4 & 7;
    int ent = idx4 >> 3;                        // block covers 32 consecutive entities
    int b0 = b4 * 4;
    if (tid == 0) wbits = 0u;
    __syncthreads();
    float4 v = ((const float4*)g_e[t + 1])[idx4];
    float4 ov = v;
    if (t == 0) {
        float* vp = &v.x;
#pragma unroll
        for (int c = 0; c < 4; c++) {
            int b = b0 + c;
            if (ent == g_ansIdx[b]) vp[c] -= g_ansVal[b] * g_gt[b];
        }
    }
    v.x = fminf(v.x, 1.f); v.y = fminf(v.y, 1.f);
    v.z = fminf(v.z, 1.f); v.w = fminf(v.w, 1.f);
    if (t >= 1) {
        float c0 = condf(t, b0), c1 = condf(t, b0 + 1);
        float c2 = condf(t, b0 + 2), c3 = condf(t, b0 + 3);
        if (c0 + c1 + c2 + c3 != 0.f) {
            float4 pv = ((const float4*)g_e[t - 1])[idx4];
            if (c0 != 0.f && pv.x > 0.9f) v.x = 0.f;
            if (c1 != 0.f && pv.y > 0.9f) v.y = 0.f;
            if (c2 != 0.f && pv.z > 0.9f) v.z = 0.f;
            if (c3 != 0.f && pv.w > 0.9f) v.w = 0.f;
        }
    }
    bool nz = (v.x != 0.f) | (v.y != 0.f) | (v.z != 0.f) | (v.w != 0.f);
    bool changed = (v.x != ov.x) | (v.y != ov.y) | (v.z != ov.z) | (v.w != ov.w);
    if (changed) ((float4*)g_e[t + 1])[idx4] = v;
    if (nz) atomicOr(&wbits, 1u << (ent & 31));
    __syncthreads();
    if (tid == 0) g_maskw[blockIdx.x] = wbits;   // ent range = [bx*32, bx*32+32)
}

// ---------------- final post: masks + e_score out + sums + active list ----------------
__global__ void __launch_bounds__(256) k_post_last(float* __restrict__ out) {
    cudaGridDependencySynchronize();
    __shared__ float tile[32][33];
    int tid = threadIdx.x;
    int e_base = blockIdx.x * 32;
    int b4 = tid & 7, el = tid >> 3;
    int b0 = b4 * 4;
    int idx4 = blockIdx.x * 256 + tid;
    const int TL = T_STEPS - 1;
    float4 v = ((const float4*)g_e[T_STEPS])[idx4];
    float4 ov = v;
    v.x = fminf(v.x, 1.f); v.y = fminf(v.y, 1.f);
    v.z = fminf(v.z, 1.f); v.w = fminf(v.w, 1.f);
    {
        float c0 = condf(TL, b0), c1 = condf(TL, b0 + 1);
        float c2 = condf(TL, b0 + 2), c3 = condf(TL, b0 + 3);
        if (c0 + c1 + c2 + c3 != 0.f) {
            float4 pv = ((const float4*)g_e[T_STEPS - 1])[idx4];
            if (c0 != 0.f && pv.x > 0.9f) v.x = 0.f;
            if (c1 != 0.f && pv.y > 0.9f) v.y = 0.f;
            if (c2 != 0.f && pv.z > 0.9f) v.z = 0.f;
            if (c3 != 0.f && pv.w > 0.9f) v.w = 0.f;
        }
    }
    {
        float m0 = m3f(b0), m1 = m3f(b0 + 1), m2 = m3f(b0 + 2), m3 = m3f(b0 + 3);
        if (m0 + m1 + m2 + m3 != 0.f) {
            float4 e0 = ((const float4*)g_e[0])[idx4];
            v.x *= 1.f - m0 * e0.x; v.y *= 1.f - m1 * e0.y;
            v.z *= 1.f - m2 * e0.z; v.w *= 1.f - m3 * e0.w;
        }
    }
    bool nz = (v.x != 0.f) | (v.y != 0.f) | (v.z != 0.f) | (v.w != 0.f);
    bool changed = (v.x != ov.x) | (v.y != ov.y) | (v.z != ov.z) | (v.w != ov.w);
    if (changed) ((float4*)g_e[T_STEPS])[idx4] = v;
    tile[b0 + 0][el] = v.x; tile[b0 + 1][el] = v.y;
    tile[b0 + 2][el] = v.z; tile[b0 + 3][el] = v.w;
    int any = __syncthreads_or(nz ? 1 : 0);
    int lane = tid & 31, warp = tid >> 5;
#pragma unroll
    for (int r = 0; r < 4; r++) {
        int b = warp + r * 8;
        out[(size_t)b * NE + e_base + lane] = tile[b][lane];
    }
    if (any && tid < 32) {
        float s = 0.f;
#pragma unroll
        for (int e = 0; e < 32; e++) s += tile[tid][e];
        if (s != 0.f) atomicAdd(&g_sums[tid], s);
        float nzv = 0.f;
#pragma unroll
        for (int b = 0; b < 32; b++) nzv += fabsf(tile[b][tid]);
        bool act = (nzv != 0.f);
        unsigned mm = __ballot_sync(0xffffffffu, act);
        if (mm) {
            int leader = __ffs(mm) - 1;
            int base = 0;
            if (tid == leader) base = atomicAdd(&g_nact, __popc(mm));
            base = __shfl_sync(0xffffffffu, base, leader);
            if (act) g_act[base + __popc(mm & ((1u << tid) - 1u))] = e_base + tid;
        }
    }
}

// ---------------- h over ACTIVE rows (per-block partials, HB=148) ----------------
__global__ void __launch_bounds__(512) k_h(const float* __restrict__ ent_emb) {
    cudaGridDependencySynchronize();
    int b = threadIdx.x & 31;
    int dg = threadIdx.x >> 5;
    float inv = 1.f / (g_sums[b] + 1e-6f);
    float acc[32];
#pragma unroll
    for (int k = 0; k < 32; k++) acc[k] = 0.f;
    int nact = g_nact;
    for (int a = blockIdx.x * 32; a < nact; a += gridDim.x * 32) {
        int aend = a + 32; if (aend > nact) aend = nact;
        for (int aa = a; aa < aend; aa++) {
            int i = g_act[aa];
            float ev = g_e[T_STEPS][(size_t)i * B + b] * inv;
            const float4* wp = (const float4*)(ent_emb + (size_t)i * DH + dg * 32);
#pragma unroll
            for (int k = 0; k < 8; k++) {
                float4 w = wp[k];
                acc[4 * k + 0] += ev * w.x; acc[4 * k + 1] += ev * w.y;
                acc[4 * k + 2] += ev * w.z; acc[4 * k + 3] += ev * w.w;
            }
        }
    }
    float* dst = g_hpart[blockIdx.x];
#pragma unroll
    for (int k = 0; k < 32; k++)
        dst[(dg * 32 + k) * B + b] = acc[k];
}

__global__ void k_hred() {
    cudaGridDependencySynchronize();
    int tid = blockIdx.x * 256 + threadIdx.x;
    if (tid >= DH * B) return;
    int b = tid & 31, d = tid >> 5;
    float s = 0.f;
    for (int blk = 0; blk < HB; blk++)
        s += g_hpart[blk][d * B + b];
    g_h[b * DH + d] = s;
}

// ---------------- pred = h @ ent_emb^T + bias (f32x2, pk2 in loop) ----------------
__global__ void __launch_bounds__(128) k_pred(const float* __restrict__ ent_emb,
                                              const float* __restrict__ ent_bias,
                                              float* __restrict__ out) {
    cudaGridDependencySynchronize();
    __shared__ float sh[32][36];
    __shared__ float se[32][256];
    int i0 = blockIdx.x * 256;
    int tid = threadIdx.x;
    int nt = tid & 31, mt = tid >> 5;
    int n0 = nt * 8, m0 = mt * 8;
    unsigned long long acc[8][4];
#pragma unroll
    for (int a = 0; a < 8; a++)
#pragma unroll
        for (int c = 0; c < 4; c++) acc[a][c] = 0ull;
    int kq = tid & 7;
    int rbase = tid >> 3;
    for (int kt = 0; kt < DH; kt += 32) {
#pragma unroll
        for (int p = 0; p < 2; p++) {
            int u = tid + p * 128;
            int m = u >> 3, kqh = u & 7;
            float4 hv = *(const float4*)(g_h + m * DH + kt + kqh * 4);
            sh[kqh * 4 + 0][m] = hv.x; sh[kqh * 4 + 1][m] = hv.y;
            sh[kqh * 4 + 2][m] = hv.z; sh[kqh * 4 + 3][m] = hv.w;
        }
#pragma unroll
        for (int r = 0; r < 16; r++) {
            int row = rbase + r * 16;
            int i = i0 + row;
            float4 v = (i < NE) ? *(const float4*)(ent_emb + (size_t)i * DH + kt + kq * 4)
                                : make_float4(0.f, 0.f, 0.f, 0.f);
            int col = row ^ (kq * 4);
            se[kq * 4 + 0][col] = v.x; se[kq * 4 + 1][col] = v.y;
            se[kq * 4 + 2][col] = v.z; se[kq * 4 + 3][col] = v.w;
        }
        __syncthreads();
#pragma unroll
        for (int kk = 0; kk < 32; kk++) {
            float4 av0 = *(const float4*)&sh[kk][m0];
            float4 av1 = *(const float4*)&sh[kk][m0 + 4];
            int q2 = (kk >> 2) * 4;
            int off = n0 ^ (q2 & 24);
            int l4 = q2 & 4;
            ulonglong2 P = *(const ulonglong2*)&se[kk][off + l4];
            ulonglong2 Q = *(const ulonglong2*)&se[kk][off + (4 ^ l4)];
            unsigned long long am[8];
            am[0] = pk2(av0.x); am[1] = pk2(av0.y); am[2] = pk2(av0.z); am[3] = pk2(av0.w);
            am[4] = pk2(av1.x); am[5] = pk2(av1.y); am[6] = pk2(av1.z); am[7] = pk2(av1.w);
#pragma unroll
            for (int a = 0; a < 8; a++) {
                fma2(acc[a][0], am[a], P.x); fma2(acc[a][1], am[a], P.y);
                fma2(acc[a][2], am[a], Q.x); fma2(acc[a][3], am[a], Q.y);
            }
        }
        __syncthreads();
    }
    int ng = i0 + n0;
    bool fast = (ng + 7 < NE);
    float bias[8];
    if (fast) {
        float4 b0 = *(const float4*)&ent_bias[ng];
        float4 b1 = *(const float4*)&ent_bias[ng + 4];
        bias[0] = b0.x; bias[1] = b0.y; bias[2] = b0.z; bias[3] = b0.w;
        bias[4] = b1.x; bias[5] = b1.y; bias[6] = b1.z; bias[7] = b1.w;
    } else {
#pragma unroll
        for (int c = 0; c < 8; c++) bias[c] = (ng + c < NE) ? ent_bias[ng + c] : 0.f;
    }
#pragma unroll
    for (int a = 0; a < 8; a++) {
        int m = m0 + a;
        float o[8];
#pragma unroll
        for (int c = 0; c < 4; c++) upk2(acc[a][c], o[2 * c], o[2 * c + 1]);
#pragma unroll
        for (int c = 0; c < 8; c++) o[c] += bias[c];
        if (fast) {
            *(float4*)&out[(size_t)m * NE + ng] = make_float4(o[0], o[1], o[2], o[3]);
            *(float4*)&out[(size_t)m * NE + ng + 4] = make_float4(o[4], o[5], o[6], o[7]);
        } else {
#pragma unroll
            for (int c = 0; c < 8; c++)
                if (ng + c < NE) out[(size_t)m * NE + ng + c] = o[c];
        }
    }
}

// ---------------- PDL launch helper ----------------
template <typename K, typename... Args>
static inline void pdl_launch(K kern, dim3 grid, dim3 block, Args... args) {
    cudaLaunchConfig_t cfg = {};
    cfg.gridDim = grid;
    cfg.blockDim = block;
    cudaLaunchAttribute attr[1];
    attr[0].id = cudaLaunchAttributeProgrammaticStreamSerialization;
    attr[0].val.programmaticStreamSerializationAllowed = 1;
    cfg.attrs = attr;
    cfg.numAttrs = 1;
    cudaLaunchKernelEx(&cfg, kern, args...);
}

// ---------------- driver (single stream, R12 ordering) ----------------
extern "C" void kernel_launch(void* const* d_in, const int* in_sizes, int n_in,
                              void* d_out, int out_size) {
    const int*   questions = (const int*)d_in[0];
    const float* e_s       = (const float*)d_in[1];
    const float* answers   = (const float*)d_in[2];
    const int*   subj      = (const int*)d_in[3];
    const int*   rel       = (const int*)d_in[4];
    const int*   obj       = (const int*)d_in[5];
    const float* rel_emb   = (const float*)d_in[6];
    const float* step_W    = (const float*)d_in[7];
    const float* step_b    = (const float*)d_in[8];
    const float* ent_emb   = (const float*)d_in[9];
    const float* ent_bias  = (const float*)d_in[10];
    float* out = (float*)d_out;

    pdl_launch(k_cq_all, dim3(T_STEPS * B * DH / 8), dim3(256),
               questions, rel_emb, step_W, step_b);
    pdl_launch(k_logits_all, dim3((T_STEPS * B * NR + 7) / 8), dim3(256), rel_emb);
    pdl_launch(k_setup, dim3(SOFT_BLKS + TRANS_BLKS + INIT_BLKS), dim3(512),
               questions, e_s, answers);

    for (int t = 0; t < T_STEPS; t++) {
        pdl_launch(k_follow, dim3((NT + 255) / 256), dim3(256), subj, rel, obj, t);
        if (t < T_STEPS - 1)
            pdl_launch(k_post, dim3(NE * B / 4 / 256), dim3(256), t);
        else
            pdl_launch(k_post_last, dim3(NE / 32), dim3(256), out);
    }

    pdl_launch(k_h, dim3(HB), dim3(512), ent_emb);
    pdl_launch(k_hred, dim3((DH * B + 255) / 256), dim3(256));
    pdl_launch(k_pred, dim3((NE + 255) / 256), dim3(128), ent_emb, ent_bias,
               out + (size_t)B * NE);
}

// round 15
// speedup vs baseline: 1.3498x; 1.3498x over previous
#include <cuda_runtime.h>
#include <math.h>

#define NE 100000
#define NR 400
#define NT 1000000
#define B  32
#define DH 512
#define T_STEPS 3
#define HB 148
#define SOFT_BLKS (T_STEPS * B)       // 96
#define TRANS_BLKS (NE / 32)          // 3125
#define INIT_BLKS  600

// ---------------- device scratch (16B-aligned) ----------------
__device__ __align__(16) float g_e[T_STEPS + 1][NE * B];
__device__ __align__(16) float g_relT[T_STEPS][NR * B];
__device__ __align__(16) float g_cqA[T_STEPS][B][DH];
__device__ __align__(16) float g_logits[T_STEPS][B][NR];
__device__ int   g_argmax[T_STEPS * B];
__device__ float g_gt[B];
__device__ __align__(16) float g_sums[B];
__device__ __align__(16) float g_h[B * DH];
__device__ unsigned char g_mask[NE];
__device__ int   g_nact;
__device__ int   g_act[NE];
__device__ int   g_ansIdx[B];
__device__ float g_ansVal[B];
__device__ __align__(16) float g_hpart[HB][DH * B];

// ---------------- f32x2 helpers ----------------
__device__ __forceinline__ unsigned long long pk2(float v) {
    unsigned long long r;
    asm("mov.b64 %0,{%1,%1};" : "=l"(r) : "f"(v));
    return r;
}
__device__ __forceinline__ void fma2(unsigned long long& d, unsigned long long a,
                                     unsigned long long b) {
    asm("fma.rn.f32x2 %0,%1,%2,%0;" : "+l"(d) : "l"(a), "l"(b));
}
__device__ __forceinline__ void upk2(unsigned long long v, float& lo, float& hi) {
    asm("mov.b64 {%0,%1},%2;" : "=f"(lo), "=f"(hi) : "l"(v));
}
__device__ __forceinline__ float dot4(float4 a, float4 b) {
    return a.x * b.x + a.y * b.y + a.z * b.z + a.w * b.w;
}
__device__ __forceinline__ float condf(int t, int b) {
    int prev = g_argmax[(t - 1) * B + b], curr = g_argmax[t * B + b];
    int d = prev - curr; if (d < 0) d = -d;
    int mn = prev < curr ? prev : curr;
    return (d == 1 && (mn & 1) == 0) ? 1.f : 0.f;
}
__device__ __forceinline__ float m3f(int b) {
    int ns = 0;
#pragma unroll
    for (int k = 0; k < T_STEPS; k++) ns += (g_argmax[k * B + b] == 0);
    return (ns == 1) ? 1.f : 0.f;
}

// ---------------- all-steps cq: warp per output (t,b,j) ----------------
__global__ void __launch_bounds__(256) k_cq_all(const int* __restrict__ questions,
                                                const float* __restrict__ rel_emb,
                                                const float* __restrict__ step_W,
                                                const float* __restrict__ step_b) {
    cudaGridDependencySynchronize();
    int w = blockIdx.x * 8 + (threadIdx.x >> 5);
    int lane = threadIdx.x & 31;
    int j = w & (DH - 1);
    int b = (w >> 9) & (B - 1);
    int t = w >> 14;
    if (t >= T_STEPS) return;
    int qi = __ldg(questions + b);
    const float4* q = (const float4*)(rel_emb + (size_t)qi * DH);
    const float4* W = (const float4*)(step_W + (size_t)t * DH * DH + (size_t)j * DH);
    float acc = 0.f;
#pragma unroll
    for (int c = 0; c < 4; c++) {
        float4 qv = __ldg(q + lane + c * 32);
        float4 wv = __ldg(W + lane + c * 32);
        acc += dot4(qv, wv);
    }
#pragma unroll
    for (int s = 16; s > 0; s >>= 1) acc += __shfl_xor_sync(0xffffffffu, acc, s);
    if (lane == 0)
        g_cqA[t][b][j] = tanhf(acc + __ldg(step_b + t * DH + j));
}

// ---------------- all-steps rel logits: warp per output (t,b,r) ----------------
__global__ void __launch_bounds__(256) k_logits_all(const float* __restrict__ rel_emb) {
    cudaGridDependencySynchronize();
    int w = blockIdx.x * 8 + (threadIdx.x >> 5);
    int lane = threadIdx.x & 31;
    int r = w % NR;
    int tb = w / NR;
    int b = tb & (B - 1);
    int t = tb >> 5;
    if (t >= T_STEPS) return;
    const float4* q = (const float4*)&g_cqA[t][b][0];
    const float4* E = (const float4*)(rel_emb + (size_t)r * DH);
    float acc = 0.f;
#pragma unroll
    for (int c = 0; c < 4; c++) {
        float4 qv = q[lane + c * 32];
        float4 ev = __ldg(E + lane + c * 32);
        acc += dot4(qv, ev);
    }
#pragma unroll
    for (int s = 16; s > 0; s >>= 1) acc += __shfl_xor_sync(0xffffffffu, acc, s);
    if (lane == 0) g_logits[t][b][r] = acc;
}

// ---------------- fused: softmax(96 blks) | transpose e_s | zero + findans ----------------
__global__ void __launch_bounds__(512) k_setup(const int* __restrict__ questions,
                                               const float* __restrict__ es,
                                               const float* __restrict__ ans) {
    cudaGridDependencySynchronize();
    int bx = blockIdx.x;
    int tid = threadIdx.x;
    if (bx < SOFT_BLKS) {
        __shared__ float red[512];
        __shared__ int   redi[512];
        int t = bx >> 5;
        int b = bx & 31;
        int r = tid;
        float logit = (r < NR) ? g_logits[t][b][r] : -1e30f;
        red[r] = logit; redi[r] = (r < NR) ? r : 0x7fffffff;
        __syncthreads();
        for (int s = 256; s > 0; s >>= 1) {
            if (r < s) {
                float a = red[r], c = red[r + s];
                int ia = redi[r], ic = redi[r + s];
                if (c > a || (c == a && ic < ia)) { red[r] = c; redi[r] = ic; }
            }
            __syncthreads();
        }
        float mx = red[0];
        int amax = redi[0];
        __syncthreads();
        float e = (r < NR) ? expf(logit - mx) : 0.f;
        red[r] = e;
        __syncthreads();
        for (int s = 256; s > 0; s >>= 1) {
            if (r < s) red[r] += red[r + s];
            __syncthreads();
        }
        float sum = red[0];
        if (r < NR) {
            float p = e / sum;
            g_relT[t][r * B + b] = p;
            if (t == 0 && r == questions[b]) g_gt[b] = p;
        }
        if (r == 0) g_argmax[t * B + b] = amax;
    } else if (bx < SOFT_BLKS + TRANS_BLKS) {
        __shared__ float tile[32][33];
        int i0 = (bx - SOFT_BLKS) * 32;
        int tx = tid & 31, ty0 = tid >> 5;
#pragma unroll
        for (int r = 0; r < 2; r++) {
            int ty = ty0 + r * 16;
            tile[ty][tx] = es[(size_t)ty * NE + i0 + tx];
        }
        __syncthreads();
#pragma unroll
        for (int r = 0; r < 2; r++) {
            int ty = ty0 + r * 16;
            float v = tile[tx][ty];
            g_e[0][(size_t)(i0 + ty) * B + tx] = v;
            unsigned m = __ballot_sync(0xffffffffu, v != 0.f);
            if (tx == 0) g_mask[i0 + ty] = (m != 0u) ? 1 : 0;
        }
    } else {
        int gtid = (bx - SOFT_BLKS - TRANS_BLKS) * 512 + tid;
        int stride = INIT_BLKS * 512;
        float4 z = make_float4(0.f, 0.f, 0.f, 0.f);
        int n4 = T_STEPS * NE * B / 4;
        float4* base = (float4*)g_e[1];
        for (int i = gtid; i < n4; i += stride) base[i] = z;
        int nf4 = B * NE / 4;
        for (int i = gtid; i < nf4; i += stride) {
            float4 v = *(const float4*)&ans[(size_t)i * 4];
            if (v.x != 0.f || v.y != 0.f || v.z != 0.f || v.w != 0.f) {
                int b = i / (NE / 4);
                int e = (i - b * (NE / 4)) * 4;
                if (v.x != 0.f) { g_ansIdx[b] = e;     g_ansVal[b] = v.x; }
                if (v.y != 0.f) { g_ansIdx[b] = e + 1; g_ansVal[b] = v.y; }
                if (v.z != 0.f) { g_ansIdx[b] = e + 2; g_ansVal[b] = v.z; }
                if (v.w != 0.f) { g_ansIdx[b] = e + 3; g_ansVal[b] = v.w; }
            }
        }
        if (gtid < B) g_sums[gtid] = 0.f;
        if (gtid == 0) g_nact = 0;
    }
}

// ---------------- follow: mask-gated scatter, 4 triples/thread (int4 ILP) ----------------
__global__ void __launch_bounds__(256) k_follow(const int* __restrict__ subj,
                                                const int* __restrict__ rel,
                                                const int* __restrict__ obj, int t) {
    cudaGridDependencySynchronize();
    int base = (blockIdx.x * 256 + threadIdx.x) * 4;
    int lane = threadIdx.x & 31;
    int4 sv = make_int4(0, 0, 0, 0);
    unsigned actm = 0;
    if (base + 3 < NT) {
        sv = *(const int4*)(subj + base);
        actm = (g_mask[sv.x] ? 1u : 0u) | (g_mask[sv.y] ? 2u : 0u)
             | (g_mask[sv.z] ? 4u : 0u) | (g_mask[sv.w] ? 8u : 0u);
    } else if (base < NT) {
        const int* sp = subj + base;
        int nrem = NT - base;
        if (nrem > 0) { sv.x = sp[0]; if (g_mask[sv.x]) actm |= 1u; }
        if (nrem > 1) { sv.y = sp[1]; if (g_mask[sv.y]) actm |= 2u; }
        if (nrem > 2) { sv.z = sp[2]; if (g_mask[sv.z]) actm |= 4u; }
    }
    const float* relT = g_relT[t];
#pragma unroll
    for (int q = 0; q < 4; q++) {
        unsigned m = __ballot_sync(0xffffffffu, (actm >> q) & 1u);
        int sq = (q == 0) ? sv.x : (q == 1) ? sv.y : (q == 2) ? sv.z : sv.w;
        while (m) {
            int j = __ffs(m) - 1; m &= m - 1;
            int ti = __shfl_sync(0xffffffffu, base, j) + q;
            int ts = __shfl_sync(0xffffffffu, sq, j);
            int tr = __ldg(rel + ti);
            int to = __ldg(obj + ti);
            float x = g_e[t][(size_t)ts * B + lane] * relT[tr * B + lane];
            if (x != 0.f) atomicAdd(&g_e[t + 1][(size_t)to * B + lane], x);
        }
    }
}

// ---------------- mid-step post (t = 0 or 1), full sweep, inline flags ----------------
__global__ void __launch_bounds__(256) k_post(int t) {
    cudaGridDependencySynchronize();
    int idx4 = blockIdx.x * 256 + threadIdx.x;
    int lane = threadIdx.x & 31;
    int b4 = idx4 & 7;
    int ent = idx4 >> 3;
    int b0 = b4 * 4;
    float4 v = ((const float4*)g_e[t + 1])[idx4];
    float4 ov = v;
    if (t == 0) {
        float* vp = &v.x;
#pragma unroll
        for (int c = 0; c < 4; c++) {
            int b = b0 + c;
            if (ent == g_ansIdx[b]) vp[c] -= g_ansVal[b] * g_gt[b];
        }
    }
    v.x = fminf(v.x, 1.f); v.y = fminf(v.y, 1.f);
    v.z = fminf(v.z, 1.f); v.w = fminf(v.w, 1.f);
    if (t >= 1) {
        float c0 = condf(t, b0), c1 = condf(t, b0 + 1);
        float c2 = condf(t, b0 + 2), c3 = condf(t, b0 + 3);
        if (c0 + c1 + c2 + c3 != 0.f) {
            float4 pv = ((const float4*)g_e[t - 1])[idx4];
            if (c0 != 0.f && pv.x > 0.9f) v.x = 0.f;
            if (c1 != 0.f && pv.y > 0.9f) v.y = 0.f;
            if (c2 != 0.f && pv.z > 0.9f) v.z = 0.f;
            if (c3 != 0.f && pv.w > 0.9f) v.w = 0.f;
        }
    }
    bool nz = (v.x != 0.f) | (v.y != 0.f) | (v.z != 0.f) | (v.w != 0.f);
    bool changed = (v.x != ov.x) | (v.y != ov.y) | (v.z != ov.z) | (v.w != ov.w);
    if (changed) ((float4*)g_e[t + 1])[idx4] = v;
    unsigned m = __ballot_sync(0xffffffffu, nz);
    if ((threadIdx.x & 7) == 0)
        g_mask[ent] = ((m >> (lane & ~7)) & 0xffu) ? 1 : 0;
}

// ---------------- final post: masks + e_score out + sums + active list ----------------
__global__ void __launch_bounds__(256) k_post_last(float* __restrict__ out) {
    cudaGridDependencySynchronize();
    __shared__ float tile[32][33];
    int tid = threadIdx.x;
    int e_base = blockIdx.x * 32;
    int b4 = tid & 7, el = tid >> 3;
    int b0 = b4 * 4;
    int idx4 = blockIdx.x * 256 + tid;
    const int TL = T_STEPS - 1;
    float4 v = ((const float4*)g_e[T_STEPS])[idx4];
    float4 ov = v;
    v.x = fminf(v.x, 1.f); v.y = fminf(v.y, 1.f);
    v.z = fminf(v.z, 1.f); v.w = fminf(v.w, 1.f);
    {
        float c0 = condf(TL, b0), c1 = condf(TL, b0 + 1);
        float c2 = condf(TL, b0 + 2), c3 = condf(TL, b0 + 3);
        if (c0 + c1 + c2 + c3 != 0.f) {
            float4 pv = ((const float4*)g_e[T_STEPS - 1])[idx4];
            if (c0 != 0.f && pv.x > 0.9f) v.x = 0.f;
            if (c1 != 0.f && pv.y > 0.9f) v.y = 0.f;
            if (c2 != 0.f && pv.z > 0.9f) v.z = 0.f;
            if (c3 != 0.f && pv.w > 0.9f) v.w = 0.f;
        }
    }
    {
        float m0 = m3f(b0), m1 = m3f(b0 + 1), m2 = m3f(b0 + 2), m3 = m3f(b0 + 3);
        if (m0 + m1 + m2 + m3 != 0.f) {
            float4 e0 = ((const float4*)g_e[0])[idx4];
            v.x *= 1.f - m0 * e0.x; v.y *= 1.f - m1 * e0.y;
            v.z *= 1.f - m2 * e0.z; v.w *= 1.f - m3 * e0.w;
        }
    }
    bool nz = (v.x != 0.f) | (v.y != 0.f) | (v.z != 0.f) | (v.w != 0.f);
    bool changed = (v.x != ov.x) | (v.y != ov.y) | (v.z != ov.z) | (v.w != ov.w);
    if (changed) ((float4*)g_e[T_STEPS])[idx4] = v;
    tile[b0 + 0][el] = v.x; tile[b0 + 1][el] = v.y;
    tile[b0 + 2][el] = v.z; tile[b0 + 3][el] = v.w;
    int any = __syncthreads_or(nz ? 1 : 0);
    int lane = tid & 31, warp = tid >> 5;
#pragma unroll
    for (int r = 0; r < 4; r++) {
        int b = warp + r * 8;
        out[(size_t)b * NE + e_base + lane] = tile[b][lane];
    }
    if (any && tid < 32) {
        float s = 0.f;
#pragma unroll
        for (int e = 0; e < 32; e++) s += tile[tid][e];
        if (s != 0.f) atomicAdd(&g_sums[tid], s);
        float nzv = 0.f;
#pragma unroll
        for (int b = 0; b < 32; b++) nzv += fabsf(tile[b][tid]);
        bool act = (nzv != 0.f);
        unsigned mm = __ballot_sync(0xffffffffu, act);
        if (mm) {
            int leader = __ffs(mm) - 1;
            int base = 0;
            if (tid == leader) base = atomicAdd(&g_nact, __popc(mm));
            base = __shfl_sync(0xffffffffu, base, leader);
            if (act) g_act[base + __popc(mm & ((1u << tid) - 1u))] = e_base + tid;
        }
    }
}

// ---------------- h over ACTIVE rows (per-block partials, HB=148) ----------------
__global__ void __launch_bounds__(512) k_h(const float* __restrict__ ent_emb) {
    cudaGridDependencySynchronize();
    int b = threadIdx.x & 31;
    int dg = threadIdx.x >> 5;
    float inv = 1.f / (g_sums[b] + 1e-6f);
    float acc[32];
#pragma unroll
    for (int k = 0; k < 32; k++) acc[k] = 0.f;
    int nact = g_nact;
    for (int a = blockIdx.x * 32; a < nact; a += gridDim.x * 32) {
        int aend = a + 32; if (aend > nact) aend = nact;
        for (int aa = a; aa < aend; aa++) {
            int i = g_act[aa];
            float ev = g_e[T_STEPS][(size_t)i * B + b] * inv;
            const float4* wp = (const float4*)(ent_emb + (size_t)i * DH + dg * 32);
#pragma unroll
            for (int k = 0; k < 8; k++) {
                float4 w = wp[k];
                acc[4 * k + 0] += ev * w.x; acc[4 * k + 1] += ev * w.y;
                acc[4 * k + 2] += ev * w.z; acc[4 * k + 3] += ev * w.w;
            }
        }
    }
    float* dst = g_hpart[blockIdx.x];
#pragma unroll
    for (int k = 0; k < 32; k++)
        dst[(dg * 32 + k) * B + b] = acc[k];
}

__global__ void k_hred() {
    cudaGridDependencySynchronize();
    int tid = blockIdx.x * 256 + threadIdx.x;
    if (tid >= DH * B) return;
    int b = tid & 31, d = tid >> 5;
    float s = 0.f;
    for (int blk = 0; blk < HB; blk++)
        s += g_hpart[blk][d * B + b];
    g_h[b * DH + d] = s;
}

// ---------------- pred = h @ ent_emb^T + bias (f32x2, pk2 in loop) ----------------
__global__ void __launch_bounds__(128) k_pred(const float* __restrict__ ent_emb,
                                              const float* __restrict__ ent_bias,
                                              float* __restrict__ out) {
    cudaGridDependencySynchronize();
    __shared__ float sh[32][36];
    __shared__ float se[32][256];
    int i0 = blockIdx.x * 256;
    int tid = threadIdx.x;
    int nt = tid & 31, mt = tid >> 5;
    int n0 = nt * 8, m0 = mt * 8;
    unsigned long long acc[8][4];
#pragma unroll
    for (int a = 0; a < 8; a++)
#pragma unroll
        for (int c = 0; c < 4; c++) acc[a][c] = 0ull;
    int kq = tid & 7;
    int rbase = tid >> 3;
    for (int kt = 0; kt < DH; kt += 32) {
#pragma unroll
        for (int p = 0; p < 2; p++) {
            int u = tid + p * 128;
            int m = u >> 3, kqh = u & 7;
            float4 hv = *(const float4*)(g_h + m * DH + kt + kqh * 4);
            sh[kqh * 4 + 0][m] = hv.x; sh[kqh * 4 + 1][m] = hv.y;
            sh[kqh * 4 + 2][m] = hv.z; sh[kqh * 4 + 3][m] = hv.w;
        }
#pragma unroll
        for (int r = 0; r < 16; r++) {
            int row = rbase + r * 16;
            int i = i0 + row;
            float4 v = (i < NE) ? *(const float4*)(ent_emb + (size_t)i * DH + kt + kq * 4)
                                : make_float4(0.f, 0.f, 0.f, 0.f);
            int col = row ^ (kq * 4);
            se[kq * 4 + 0][col] = v.x; se[kq * 4 + 1][col] = v.y;
            se[kq * 4 + 2][col] = v.z; se[kq * 4 + 3][col] = v.w;
        }
        __syncthreads();
#pragma unroll
        for (int kk = 0; kk < 32; kk++) {
            float4 av0 = *(const float4*)&sh[kk][m0];
            float4 av1 = *(const float4*)&sh[kk][m0 + 4];
            int q2 = (kk >> 2) * 4;
            int off = n0 ^ (q2 & 24);
            int l4 = q2 & 4;
            ulonglong2 P = *(const ulonglong2*)&se[kk][off + l4];
            ulonglong2 Q = *(const ulonglong2*)&se[kk][off + (4 ^ l4)];
            unsigned long long am[8];
            am[0] = pk2(av0.x); am[1] = pk2(av0.y); am[2] = pk2(av0.z); am[3] = pk2(av0.w);
            am[4] = pk2(av1.x); am[5] = pk2(av1.y); am[6] = pk2(av1.z); am[7] = pk2(av1.w);
#pragma unroll
            for (int a = 0; a < 8; a++) {
                fma2(acc[a][0], am[a], P.x); fma2(acc[a][1], am[a], P.y);
                fma2(acc[a][2], am[a], Q.x); fma2(acc[a][3], am[a], Q.y);
            }
        }
        __syncthreads();
    }
    int ng = i0 + n0;
    bool fast = (ng + 7 < NE);
    float bias[8];
    if (fast) {
        float4 b0 = *(const float4*)&ent_bias[ng];
        float4 b1 = *(const float4*)&ent_bias[ng + 4];
        bias[0] = b0.x; bias[1] = b0.y; bias[2] = b0.z; bias[3] = b0.w;
        bias[4] = b1.x; bias[5] = b1.y; bias[6] = b1.z; bias[7] = b1.w;
    } else {
#pragma unroll
        for (int c = 0; c < 8; c++) bias[c] = (ng + c < NE) ? ent_bias[ng + c] : 0.f;
    }
#pragma unroll
    for (int a = 0; a < 8; a++) {
        int m = m0 + a;
        float o[8];
#pragma unroll
        for (int c = 0; c < 4; c++) upk2(acc[a][c], o[2 * c], o[2 * c + 1]);
#pragma unroll
        for (int c = 0; c < 8; c++) o[c] += bias[c];
        if (fast) {
            *(float4*)&out[(size_t)m * NE + ng] = make_float4(o[0], o[1], o[2], o[3]);
            *(float4*)&out[(size_t)m * NE + ng + 4] = make_float4(o[4], o[5], o[6], o[7]);
        } else {
#pragma unroll
            for (int c = 0; c < 8; c++)
                if (ng + c < NE) out[(size_t)m * NE + ng + c] = o[c];
        }
    }
}

// ---------------- PDL launch helper ----------------
template <typename K, typename... Args>
static inline void pdl_launch(K kern, dim3 grid, dim3 block, Args... args) {
    cudaLaunchConfig_t cfg = {};
    cfg.gridDim = grid;
    cfg.blockDim = block;
    cudaLaunchAttribute attr[1];
    attr[0].id = cudaLaunchAttributeProgrammaticStreamSerialization;
    attr[0].val.programmaticStreamSerializationAllowed = 1;
    cfg.attrs = attr;
    cfg.numAttrs = 1;
    cudaLaunchKernelEx(&cfg, kern, args...);
}

// ---------------- driver ----------------
extern "C" void kernel_launch(void* const* d_in, const int* in_sizes, int n_in,
                              void* d_out, int out_size) {
    const int*   questions = (const int*)d_in[0];
    const float* e_s       = (const float*)d_in[1];
    const float* answers   = (const float*)d_in[2];
    const int*   subj      = (const int*)d_in[3];
    const int*   rel       = (const int*)d_in[4];
    const int*   obj       = (const int*)d_in[5];
    const float* rel_emb   = (const float*)d_in[6];
    const float* step_W    = (const float*)d_in[7];
    const float* step_b    = (const float*)d_in[8];
    const float* ent_emb   = (const float*)d_in[9];
    const float* ent_bias  = (const float*)d_in[10];
    float* out = (float*)d_out;

    pdl_launch(k_cq_all, dim3(T_STEPS * B * DH / 8), dim3(256),
               questions, rel_emb, step_W, step_b);
    pdl_launch(k_logits_all, dim3((T_STEPS * B * NR + 7) / 8), dim3(256), rel_emb);
    pdl_launch(k_setup, dim3(SOFT_BLKS + TRANS_BLKS + INIT_BLKS), dim3(512),
               questions, e_s, answers);

    for (int t = 0; t < T_STEPS; t++) {
        pdl_launch(k_follow, dim3((NT + 1023) / 1024), dim3(256), subj, rel, obj, t);
        if (t < T_STEPS - 1)
            pdl_launch(k_post, dim3(NE * B / 4 / 256), dim3(256), t);
        else
            pdl_launch(k_post_last, dim3(NE / 32), dim3(256), out);
    }

    pdl_launch(k_h, dim3(HB), dim3(512), ent_emb);
    pdl_launch(k_hred, dim3((DH * B + 255) / 256), dim3(256));
    pdl_launch(k_pred, dim3((NE + 255) / 256), dim3(128), ent_emb, ent_bias,
               out + (size_t)B * NE);
}

// round 16
// speedup vs baseline: 1.3768x; 1.0200x over previous
#include <cuda_runtime.h>
#include <math.h>

#define NE 100000
#define NR 400
#define NT 1000000
#define B  32
#define DH 512
#define T_STEPS 3
#define HB 148
#define SOFT_BLKS (T_STEPS * B)       // 96
#define TRANS_BLKS (NE / 32)          // 3125
#define INIT_BLKS  600

// ---------------- device scratch (16B-aligned) ----------------
__device__ __align__(16) float g_e[T_STEPS + 1][NE * B];
__device__ __align__(16) float g_relT[T_STEPS][NR * B];
__device__ __align__(16) float g_cqA[T_STEPS][B][DH];
__device__ __align__(16) float g_logits[T_STEPS][B][NR];
__device__ int   g_argmax[T_STEPS * B];
__device__ float g_gt[B];
__device__ __align__(16) float g_sums[B];
__device__ __align__(16) float g_h[B * DH];
__device__ unsigned char g_mask[NE];
__device__ int   g_nact;
__device__ int   g_act[NE];
__device__ int   g_ansIdx[B];
__device__ float g_ansVal[B];
__device__ __align__(16) float g_hpart[HB][DH * B];

// ---------------- f32x2 helpers ----------------
__device__ __forceinline__ unsigned long long pk2(float v) {
    unsigned long long r;
    asm("mov.b64 %0,{%1,%1};" : "=l"(r) : "f"(v));
    return r;
}
__device__ __forceinline__ void fma2(unsigned long long& d, unsigned long long a,
                                     unsigned long long b) {
    asm("fma.rn.f32x2 %0,%1,%2,%0;" : "+l"(d) : "l"(a), "l"(b));
}
__device__ __forceinline__ void upk2(unsigned long long v, float& lo, float& hi) {
    asm("mov.b64 {%0,%1},%2;" : "=f"(lo), "=f"(hi) : "l"(v));
}
__device__ __forceinline__ float dot4(float4 a, float4 b) {
    return a.x * b.x + a.y * b.y + a.z * b.z + a.w * b.w;
}
__device__ __forceinline__ float condf(int t, int b) {
    int prev = g_argmax[(t - 1) * B + b], curr = g_argmax[t * B + b];
    int d = prev - curr; if (d < 0) d = -d;
    int mn = prev < curr ? prev : curr;
    return (d == 1 && (mn & 1) == 0) ? 1.f : 0.f;
}
__device__ __forceinline__ float m3f(int b) {
    int ns = 0;
#pragma unroll
    for (int k = 0; k < T_STEPS; k++) ns += (g_argmax[k * B + b] == 0);
    return (ns == 1) ? 1.f : 0.f;
}

// ---------------- all-steps cq: warp per output (t,b,j) ----------------
__global__ void __launch_bounds__(256) k_cq_all(const int* __restrict__ questions,
                                                const float* __restrict__ rel_emb,
                                                const float* __restrict__ step_W,
                                                const float* __restrict__ step_b) {
    cudaGridDependencySynchronize();
    int w = blockIdx.x * 8 + (threadIdx.x >> 5);
    int lane = threadIdx.x & 31;
    int j = w & (DH - 1);
    int b = (w >> 9) & (B - 1);
    int t = w >> 14;
    if (t >= T_STEPS) return;
    int qi = __ldg(questions + b);
    const float4* q = (const float4*)(rel_emb + (size_t)qi * DH);
    const float4* W = (const float4*)(step_W + (size_t)t * DH * DH + (size_t)j * DH);
    float acc = 0.f;
#pragma unroll
    for (int c = 0; c < 4; c++) {
        float4 qv = __ldg(q + lane + c * 32);
        float4 wv = __ldg(W + lane + c * 32);
        acc += dot4(qv, wv);
    }
#pragma unroll
    for (int s = 16; s > 0; s >>= 1) acc += __shfl_xor_sync(0xffffffffu, acc, s);
    if (lane == 0)
        g_cqA[t][b][j] = tanhf(acc + __ldg(step_b + t * DH + j));
}

// ---------------- all-steps rel logits: warp per output (t,b,r) ----------------
__global__ void __launch_bounds__(256) k_logits_all(const float* __restrict__ rel_emb) {
    cudaGridDependencySynchronize();
    int w = blockIdx.x * 8 + (threadIdx.x >> 5);
    int lane = threadIdx.x & 31;
    int r = w % NR;
    int tb = w / NR;
    int b = tb & (B - 1);
    int t = tb >> 5;
    if (t >= T_STEPS) return;
    const float4* q = (const float4*)&g_cqA[t][b][0];
    const float4* E = (const float4*)(rel_emb + (size_t)r * DH);
    float acc = 0.f;
#pragma unroll
    for (int c = 0; c < 4; c++) {
        float4 qv = q[lane + c * 32];
        float4 ev = __ldg(E + lane + c * 32);
        acc += dot4(qv, ev);
    }
#pragma unroll
    for (int s = 16; s > 0; s >>= 1) acc += __shfl_xor_sync(0xffffffffu, acc, s);
    if (lane == 0) g_logits[t][b][r] = acc;
}

// ---------------- fused: softmax(96 blks) | transpose e_s | zero + findans ----------------
__global__ void __launch_bounds__(512) k_setup(const int* __restrict__ questions,
                                               const float* __restrict__ es,
                                               const float* __restrict__ ans) {
    cudaGridDependencySynchronize();
    int bx = blockIdx.x;
    int tid = threadIdx.x;
    if (bx < SOFT_BLKS) {
        __shared__ float red[512];
        __shared__ int   redi[512];
        int t = bx >> 5;
        int b = bx & 31;
        int r = tid;
        float logit = (r < NR) ? g_logits[t][b][r] : -1e30f;
        red[r] = logit; redi[r] = (r < NR) ? r : 0x7fffffff;
        __syncthreads();
        for (int s = 256; s > 0; s >>= 1) {
            if (r < s) {
                float a = red[r], c = red[r + s];
                int ia = redi[r], ic = redi[r + s];
                if (c > a || (c == a && ic < ia)) { red[r] = c; redi[r] = ic; }
            }
            __syncthreads();
        }
        float mx = red[0];
        int amax = redi[0];
        __syncthreads();
        float e = (r < NR) ? expf(logit - mx) : 0.f;
        red[r] = e;
        __syncthreads();
        for (int s = 256; s > 0; s >>= 1) {
            if (r < s) red[r] += red[r + s];
            __syncthreads();
        }
        float sum = red[0];
        if (r < NR) {
            float p = e / sum;
            g_relT[t][r * B + b] = p;
            if (t == 0 && r == questions[b]) g_gt[b] = p;
        }
        if (r == 0) g_argmax[t * B + b] = amax;
    } else if (bx < SOFT_BLKS + TRANS_BLKS) {
        __shared__ float tile[32][33];
        int i0 = (bx - SOFT_BLKS) * 32;
        int tx = tid & 31, ty0 = tid >> 5;
#pragma unroll
        for (int r = 0; r < 2; r++) {
            int ty = ty0 + r * 16;
            tile[ty][tx] = es[(size_t)ty * NE + i0 + tx];
        }
        __syncthreads();
#pragma unroll
        for (int r = 0; r < 2; r++) {
            int ty = ty0 + r * 16;
            float v = tile[tx][ty];
            g_e[0][(size_t)(i0 + ty) * B + tx] = v;
            unsigned m = __ballot_sync(0xffffffffu, v != 0.f);
            if (tx == 0) g_mask[i0 + ty] = (m != 0u) ? 1 : 0;
        }
    } else {
        int gtid = (bx - SOFT_BLKS - TRANS_BLKS) * 512 + tid;
        int stride = INIT_BLKS * 512;
        float4 z = make_float4(0.f, 0.f, 0.f, 0.f);
        int n4 = T_STEPS * NE * B / 4;
        float4* base = (float4*)g_e[1];
        for (int i = gtid; i < n4; i += stride) base[i] = z;
        int nf4 = B * NE / 4;
        for (int i = gtid; i < nf4; i += stride) {
            float4 v = *(const float4*)&ans[(size_t)i * 4];
            if (v.x != 0.f || v.y != 0.f || v.z != 0.f || v.w != 0.f) {
                int b = i / (NE / 4);
                int e = (i - b * (NE / 4)) * 4;
                if (v.x != 0.f) { g_ansIdx[b] = e;     g_ansVal[b] = v.x; }
                if (v.y != 0.f) { g_ansIdx[b] = e + 1; g_ansVal[b] = v.y; }
                if (v.z != 0.f) { g_ansIdx[b] = e + 2; g_ansVal[b] = v.z; }
                if (v.w != 0.f) { g_ansIdx[b] = e + 3; g_ansVal[b] = v.w; }
            }
        }
        if (gtid < B) g_sums[gtid] = 0.f;
        if (gtid == 0) g_nact = 0;
    }
}

// ---------------- follow: mask-gated scatter, 4 triples/thread (int4 ILP) ----------------
__global__ void __launch_bounds__(256) k_follow(const int* __restrict__ subj,
                                                const int* __restrict__ rel,
                                                const int* __restrict__ obj, int t) {
    cudaGridDependencySynchronize();
    int base = (blockIdx.x * 256 + threadIdx.x) * 4;
    int lane = threadIdx.x & 31;
    int4 sv = make_int4(0, 0, 0, 0);
    unsigned actm = 0;
    if (base + 3 < NT) {
        sv = *(const int4*)(subj + base);
        actm = (g_mask[sv.x] ? 1u : 0u) | (g_mask[sv.y] ? 2u : 0u)
             | (g_mask[sv.z] ? 4u : 0u) | (g_mask[sv.w] ? 8u : 0u);
    } else if (base < NT) {
        const int* sp = subj + base;
        int nrem = NT - base;
        if (nrem > 0) { sv.x = sp[0]; if (g_mask[sv.x]) actm |= 1u; }
        if (nrem > 1) { sv.y = sp[1]; if (g_mask[sv.y]) actm |= 2u; }
        if (nrem > 2) { sv.z = sp[2]; if (g_mask[sv.z]) actm |= 4u; }
    }
    const float* relT = g_relT[t];
#pragma unroll
    for (int q = 0; q < 4; q++) {
        unsigned m = __ballot_sync(0xffffffffu, (actm >> q) & 1u);
        int sq = (q == 0) ? sv.x : (q == 1) ? sv.y : (q == 2) ? sv.z : sv.w;
        while (m) {
            int j = __ffs(m) - 1; m &= m - 1;
            int ti = __shfl_sync(0xffffffffu, base, j) + q;
            int ts = __shfl_sync(0xffffffffu, sq, j);
            int tr = __ldg(rel + ti);
            int to = __ldg(obj + ti);
            float x = g_e[t][(size_t)ts * B + lane] * relT[tr * B + lane];
            if (x != 0.f) atomicAdd(&g_e[t + 1][(size_t)to * B + lane], x);
        }
    }
}

// ---------------- mid-step post (t = 0 or 1), full sweep, inline flags ----------------
__global__ void __launch_bounds__(256) k_post(int t) {
    cudaGridDependencySynchronize();
    int idx4 = blockIdx.x * 256 + threadIdx.x;
    int lane = threadIdx.x & 31;
    int b4 = idx4 & 7;
    int ent = idx4 >> 3;
    int b0 = b4 * 4;
    float4 v = ((const float4*)g_e[t + 1])[idx4];
    float4 ov = v;
    if (t == 0) {
        float* vp = &v.x;
#pragma unroll
        for (int c = 0; c < 4; c++) {
            int b = b0 + c;
            if (ent == g_ansIdx[b]) vp[c] -= g_ansVal[b] * g_gt[b];
        }
    }
    v.x = fminf(v.x, 1.f); v.y = fminf(v.y, 1.f);
    v.z = fminf(v.z, 1.f); v.w = fminf(v.w, 1.f);
    if (t >= 1) {
        float c0 = condf(t, b0), c1 = condf(t, b0 + 1);
        float c2 = condf(t, b0 + 2), c3 = condf(t, b0 + 3);
        if (c0 + c1 + c2 + c3 != 0.f) {
            float4 pv = ((const float4*)g_e[t - 1])[idx4];
            if (c0 != 0.f && pv.x > 0.9f) v.x = 0.f;
            if (c1 != 0.f && pv.y > 0.9f) v.y = 0.f;
            if (c2 != 0.f && pv.z > 0.9f) v.z = 0.f;
            if (c3 != 0.f && pv.w > 0.9f) v.w = 0.f;
        }
    }
    bool nz = (v.x != 0.f) | (v.y != 0.f) | (v.z != 0.f) | (v.w != 0.f);
    bool changed = (v.x != ov.x) | (v.y != ov.y) | (v.z != ov.z) | (v.w != ov.w);
    if (changed) ((float4*)g_e[t + 1])[idx4] = v;
    unsigned m = __ballot_sync(0xffffffffu, nz);
    if ((threadIdx.x & 7) == 0)
        g_mask[ent] = ((m >> (lane & ~7)) & 0xffu) ? 1 : 0;
}

// ---------------- final post: masks + e_score out + sums + active list ----------------
__global__ void __launch_bounds__(256) k_post_last(float* __restrict__ out) {
    cudaGridDependencySynchronize();
    __shared__ float tile[32][33];
    int tid = threadIdx.x;
    int e_base = blockIdx.x * 32;
    int b4 = tid & 7, el = tid >> 3;
    int b0 = b4 * 4;
    int idx4 = blockIdx.x * 256 + tid;
    const int TL = T_STEPS - 1;
    float4 v = ((const float4*)g_e[T_STEPS])[idx4];
    float4 ov = v;
    v.x = fminf(v.x, 1.f); v.y = fminf(v.y, 1.f);
    v.z = fminf(v.z, 1.f); v.w = fminf(v.w, 1.f);
    {
        float c0 = condf(TL, b0), c1 = condf(TL, b0 + 1);
        float c2 = condf(TL, b0 + 2), c3 = condf(TL, b0 + 3);
        if (c0 + c1 + c2 + c3 != 0.f) {
            float4 pv = ((const float4*)g_e[T_STEPS - 1])[idx4];
            if (c0 != 0.f && pv.x > 0.9f) v.x = 0.f;
            if (c1 != 0.f && pv.y > 0.9f) v.y = 0.f;
            if (c2 != 0.f && pv.z > 0.9f) v.z = 0.f;
            if (c3 != 0.f && pv.w > 0.9f) v.w = 0.f;
        }
    }
    {
        float m0 = m3f(b0), m1 = m3f(b0 + 1), m2 = m3f(b0 + 2), m3 = m3f(b0 + 3);
        if (m0 + m1 + m2 + m3 != 0.f) {
            float4 e0 = ((const float4*)g_e[0])[idx4];
            v.x *= 1.f - m0 * e0.x; v.y *= 1.f - m1 * e0.y;
            v.z *= 1.f - m2 * e0.z; v.w *= 1.f - m3 * e0.w;
        }
    }
    bool nz = (v.x != 0.f) | (v.y != 0.f) | (v.z != 0.f) | (v.w != 0.f);
    bool changed = (v.x != ov.x) | (v.y != ov.y) | (v.z != ov.z) | (v.w != ov.w);
    if (changed) ((float4*)g_e[T_STEPS])[idx4] = v;
    tile[b0 + 0][el] = v.x; tile[b0 + 1][el] = v.y;
    tile[b0 + 2][el] = v.z; tile[b0 + 3][el] = v.w;
    int any = __syncthreads_or(nz ? 1 : 0);
    int lane = tid & 31, warp = tid >> 5;
#pragma unroll
    for (int r = 0; r < 4; r++) {
        int b = warp + r * 8;
        out[(size_t)b * NE + e_base + lane] = tile[b][lane];
    }
    if (any && tid < 32) {
        float s = 0.f;
#pragma unroll
        for (int e = 0; e < 32; e++) s += tile[tid][e];
        if (s != 0.f) atomicAdd(&g_sums[tid], s);
        float nzv = 0.f;
#pragma unroll
        for (int b = 0; b < 32; b++) nzv += fabsf(tile[b][tid]);
        bool act = (nzv != 0.f);
        unsigned mm = __ballot_sync(0xffffffffu, act);
        if (mm) {
            int leader = __ffs(mm) - 1;
            int base = 0;
            if (tid == leader) base = atomicAdd(&g_nact, __popc(mm));
            base = __shfl_sync(0xffffffffu, base, leader);
            if (act) g_act[base + __popc(mm & ((1u << tid) - 1u))] = e_base + tid;
        }
    }
}

// ---------------- h over ACTIVE rows (per-block partials, HB=148) ----------------
__global__ void __launch_bounds__(512) k_h(const float* __restrict__ ent_emb) {
    cudaGridDependencySynchronize();
    int b = threadIdx.x & 31;
    int dg = threadIdx.x >> 5;
    float inv = 1.f / (g_sums[b] + 1e-6f);
    float acc[32];
#pragma unroll
    for (int k = 0; k < 32; k++) acc[k] = 0.f;
    int nact = g_nact;
    for (int a = blockIdx.x * 32; a < nact; a += gridDim.x * 32) {
        int aend = a + 32; if (aend > nact) aend = nact;
        for (int aa = a; aa < aend; aa++) {
            int i = g_act[aa];
            float ev = g_e[T_STEPS][(size_t)i * B + b] * inv;
            const float4* wp = (const float4*)(ent_emb + (size_t)i * DH + dg * 32);
#pragma unroll
            for (int k = 0; k < 8; k++) {
                float4 w = wp[k];
                acc[4 * k + 0] += ev * w.x; acc[4 * k + 1] += ev * w.y;
                acc[4 * k + 2] += ev * w.z; acc[4 * k + 3] += ev * w.w;
            }
        }
    }
    float* dst = g_hpart[blockIdx.x];
#pragma unroll
    for (int k = 0; k < 32; k++)
        dst[(dg * 32 + k) * B + b] = acc[k];
}

__global__ void k_hred() {
    cudaGridDependencySynchronize();
    int tid = blockIdx.x * 256 + threadIdx.x;
    if (tid >= DH * B) return;
    int b = tid & 31, d = tid >> 5;
    float s = 0.f;
    for (int blk = 0; blk < HB; blk++)
        s += g_hpart[blk][d * B + b];
    g_h[b * DH + d] = s;
}

// ---------------- pred = h @ ent_emb^T + bias (f32x2, register-prefetch pipeline) ----------------
__global__ void __launch_bounds__(128) k_pred(const float* __restrict__ ent_emb,
                                              const float* __restrict__ ent_bias,
                                              float* __restrict__ out) {
    cudaGridDependencySynchronize();
    __shared__ float sh[32][36];
    __shared__ float se[32][256];
    int i0 = blockIdx.x * 256;
    int tid = threadIdx.x;
    int nt = tid & 31, mt = tid >> 5;
    int n0 = nt * 8, m0 = mt * 8;
    unsigned long long acc[8][4];
#pragma unroll
    for (int a = 0; a < 8; a++)
#pragma unroll
        for (int c = 0; c < 4; c++) acc[a][c] = 0ull;
    int kq = tid & 7;
    int rbase = tid >> 3;

    // prologue: load tile kt=0 directly into smem
    {
        const int kt = 0;
#pragma unroll
        for (int p = 0; p < 2; p++) {
            int u = tid + p * 128;
            int m = u >> 3, kqh = u & 7;
            float4 hv = *(const float4*)(g_h + m * DH + kt + kqh * 4);
            sh[kqh * 4 + 0][m] = hv.x; sh[kqh * 4 + 1][m] = hv.y;
            sh[kqh * 4 + 2][m] = hv.z; sh[kqh * 4 + 3][m] = hv.w;
        }
#pragma unroll
        for (int r = 0; r < 16; r++) {
            int row = rbase + r * 16;
            int i = i0 + row;
            float4 v = (i < NE) ? *(const float4*)(ent_emb + (size_t)i * DH + kt + kq * 4)
                                : make_float4(0.f, 0.f, 0.f, 0.f);
            int col = row ^ (kq * 4);
            se[kq * 4 + 0][col] = v.x; se[kq * 4 + 1][col] = v.y;
            se[kq * 4 + 2][col] = v.z; se[kq * 4 + 3][col] = v.w;
        }
    }
    __syncthreads();

    for (int kt = 0; kt < DH; kt += 32) {
        // prefetch next k-tile into registers BEFORE the FMA loop (latency overlap)
        float4 pre_h[2];
        float4 pre_e[16];
        bool more = (kt + 32 < DH);
        if (more) {
            int ktn = kt + 32;
#pragma unroll
            for (int p = 0; p < 2; p++) {
                int u = tid + p * 128;
                int m = u >> 3, kqh = u & 7;
                pre_h[p] = *(const float4*)(g_h + m * DH + ktn + kqh * 4);
            }
#pragma unroll
            for (int r = 0; r < 16; r++) {
                int row = rbase + r * 16;
                int i = i0 + row;
                pre_e[r] = (i < NE)
                    ? *(const float4*)(ent_emb + (size_t)i * DH + ktn + kq * 4)
                    : make_float4(0.f, 0.f, 0.f, 0.f);
            }
        }
        // FMA on current tile (loads above in flight)
#pragma unroll
        for (int kk = 0; kk < 32; kk++) {
            float4 av0 = *(const float4*)&sh[kk][m0];
            float4 av1 = *(const float4*)&sh[kk][m0 + 4];
            int q2 = (kk >> 2) * 4;
            int off = n0 ^ (q2 & 24);
            int l4 = q2 & 4;
            ulonglong2 P = *(const ulonglong2*)&se[kk][off + l4];
            ulonglong2 Q = *(const ulonglong2*)&se[kk][off + (4 ^ l4)];
            unsigned long long am[8];
            am[0] = pk2(av0.x); am[1] = pk2(av0.y); am[2] = pk2(av0.z); am[3] = pk2(av0.w);
            am[4] = pk2(av1.x); am[5] = pk2(av1.y); am[6] = pk2(av1.z); am[7] = pk2(av1.w);
#pragma unroll
            for (int a = 0; a < 8; a++) {
                fma2(acc[a][0], am[a], P.x); fma2(acc[a][1], am[a], P.y);
                fma2(acc[a][2], am[a], Q.x); fma2(acc[a][3], am[a], Q.y);
            }
        }
        __syncthreads();   // everyone done reading current tile
        if (more) {
#pragma unroll
            for (int p = 0; p < 2; p++) {
                int u = tid + p * 128;
                int m = u >> 3, kqh = u & 7;
                sh[kqh * 4 + 0][m] = pre_h[p].x; sh[kqh * 4 + 1][m] = pre_h[p].y;
                sh[kqh * 4 + 2][m] = pre_h[p].z; sh[kqh * 4 + 3][m] = pre_h[p].w;
            }
#pragma unroll
            for (int r = 0; r < 16; r++) {
                int row = rbase + r * 16;
                int col = row ^ (kq * 4);
                se[kq * 4 + 0][col] = pre_e[r].x; se[kq * 4 + 1][col] = pre_e[r].y;
                se[kq * 4 + 2][col] = pre_e[r].z; se[kq * 4 + 3][col] = pre_e[r].w;
            }
            __syncthreads();   // next tile ready
        }
    }
    int ng = i0 + n0;
    bool fast = (ng + 7 < NE);
    float bias[8];
    if (fast) {
        float4 b0 = *(const float4*)&ent_bias[ng];
        float4 b1 = *(const float4*)&ent_bias[ng + 4];
        bias[0] = b0.x; bias[1] = b0.y; bias[2] = b0.z; bias[3] = b0.w;
        bias[4] = b1.x; bias[5] = b1.y; bias[6] = b1.z; bias[7] = b1.w;
    } else {
#pragma unroll
        for (int c = 0; c < 8; c++) bias[c] = (ng + c < NE) ? ent_bias[ng + c] : 0.f;
    }
#pragma unroll
    for (int a = 0; a < 8; a++) {
        int m = m0 + a;
        float o[8];
#pragma unroll
        for (int c = 0; c < 4; c++) upk2(acc[a][c], o[2 * c], o[2 * c + 1]);
#pragma unroll
        for (int c = 0; c < 8; c++) o[c] += bias[c];
        if (fast) {
            *(float4*)&out[(size_t)m * NE + ng] = make_float4(o[0], o[1], o[2], o[3]);
            *(float4*)&out[(size_t)m * NE + ng + 4] = make_float4(o[4], o[5], o[6], o[7]);
        } else {
#pragma unroll
            for (int c = 0; c < 8; c++)
                if (ng + c < NE) out[(size_t)m * NE + ng + c] = o[c];
        }
    }
}

// ---------------- PDL launch helper ----------------
template <typename K, typename... Args>
static inline void pdl_launch(K kern, dim3 grid, dim3 block, Args... args) {
    cudaLaunchConfig_t cfg = {};
    cfg.gridDim = grid;
    cfg.blockDim = block;
    cudaLaunchAttribute attr[1];
    attr[0].id = cudaLaunchAttributeProgrammaticStreamSerialization;
    attr[0].val.programmaticStreamSerializationAllowed = 1;
    cfg.attrs = attr;
    cfg.numAttrs = 1;
    cudaLaunchKernelEx(&cfg, kern, args...);
}

// ---------------- driver ----------------
extern "C" void kernel_launch(void* const* d_in, const int* in_sizes, int n_in,
                              void* d_out, int out_size) {
    const int*   questions = (const int*)d_in[0];
    const float* e_s       = (const float*)d_in[1];
    const float* answers   = (const float*)d_in[2];
    const int*   subj      = (const int*)d_in[3];
    const int*   rel       = (const int*)d_in[4];
    const int*   obj       = (const int*)d_in[5];
    const float* rel_emb   = (const float*)d_in[6];
    const float* step_W    = (const float*)d_in[7];
    const float* step_b    = (const float*)d_in[8];
    const float* ent_emb   = (const float*)d_in[9];
    const float* ent_bias  = (const float*)d_in[10];
    float* out = (float*)d_out;

    pdl_launch(k_cq_all, dim3(T_STEPS * B * DH / 8), dim3(256),
               questions, rel_emb, step_W, step_b);
    pdl_launch(k_logits_all, dim3((T_STEPS * B * NR + 7) / 8), dim3(256), rel_emb);
    pdl_launch(k_setup, dim3(SOFT_BLKS + TRANS_BLKS + INIT_BLKS), dim3(512),
               questions, e_s, answers);

    for (int t = 0; t < T_STEPS; t++) {
        pdl_launch(k_follow, dim3((NT + 1023) / 1024), dim3(256), subj, rel, obj, t);
        if (t < T_STEPS - 1)
            pdl_launch(k_post, dim3(NE * B / 4 / 256), dim3(256), t);
        else
            pdl_launch(k_post_last, dim3(NE / 32), dim3(256), out);
    }

    pdl_launch(k_h, dim3(HB), dim3(512), ent_emb);
    pdl_launch(k_hred, dim3((DH * B + 255) / 256), dim3(256));
    pdl_launch(k_pred, dim3((NE + 255) / 256), dim3(128), ent_emb, ent_bias,
               out + (size_t)B * NE);
}